// round 1
// baseline (speedup 1.0000x reference)
#include <cuda_runtime.h>

typedef unsigned long long u64;

constexpr int CB = 1024;   // batch
constexpr int CF = 4096;   // feature
constexpr int CV = 20000;  // vocab
constexpr int CE = 512;    // embed dim
constexpr int CH = 1024;   // hidden
constexpr int CL = 20;     // sentence length
constexpr int CD = 4;      // distractors

// ---------------- scratch (static device globals; no allocation) ----------------
__device__ float g_logits[(size_t)CB * CV];     // 81.9 MB
__device__ float g_gates[(size_t)CB * 4 * CH];  // 16.8 MB
__device__ float g_hs[CB * CH];
__device__ float g_cs[CB * CH];
__device__ float g_hr[CB * CH];
__device__ float g_cr[CB * CH];
__device__ float g_lp[CB];
__device__ float g_r[(size_t)CB * CF];          // 16.8 MB
__device__ float g_ts[(size_t)CB * CB];
__device__ float g_ds[(size_t)CD * CB * CB];    // 16.8 MB
__device__ float g_rowloss[CB];
__device__ float g_rowcorr[CB];
__device__ int   g_msg[CL * CB];
__device__ int   g_tok0[CB];

// ---------------- packed f32x2 helpers (Blackwell FFMA2 via PTX) ----------------
__device__ __forceinline__ u64 pk2(float lo, float hi) {
    u64 r; asm("mov.b64 %0, {%1, %2};" : "=l"(r) : "f"(lo), "f"(hi)); return r;
}
__device__ __forceinline__ float2 up2(u64 v) {
    float2 r; asm("mov.b64 {%0, %1}, %2;" : "=f"(r.x), "=f"(r.y) : "l"(v)); return r;
}
__device__ __forceinline__ u64 ffma2(u64 a, u64 b, u64 c) {
    u64 d; asm("fma.rn.f32x2 %0, %1, %2, %3;" : "=l"(d) : "l"(a), "l"(b), "l"(c)); return d;
}

// ---------------------------------------------------------------------------
// Generic NT SGEMM: C[M,N] = A1[M,K1] * W1[N,K1]^T (+ A2[M,K2]*W2[N,K2]^T)
//                   + bias1[n] + bias2[n]
// A1 rows optionally gathered through idx1 (row m reads A1 + idx1[m]*K1).
// M, K multiples of 16 and M multiple of 128; N arbitrary multiple of 8.
// 128x128 block tile, BK=16, 256 threads, 8x8 thread tile, f32x2 FMAs,
// double-buffered shared memory.
// ---------------------------------------------------------------------------
__global__ __launch_bounds__(256, 2)
void sgemm_nt(int M, int N,
              const float* __restrict__ A1, int K1, const int* __restrict__ idx1,
              const float* __restrict__ A2, int K2,
              const float* __restrict__ W1, const float* __restrict__ W2,
              const float* __restrict__ bias1, const float* __restrict__ bias2,
              float* __restrict__ C)
{
    __shared__ float As[2][16][128];
    __shared__ float Ws[2][16][128];

    const int tid  = threadIdx.x;
    const int tx   = tid & 15, ty = tid >> 4;
    const int row0 = ty * 8;
    const int col0 = tx * 8;
    const int bm0  = blockIdx.y * 128;
    const int bn0  = blockIdx.x * 128;

    // per-thread global load coordinates: 2 float4 per tile side
    const int lr0 = tid >> 2;        // 0..63
    const int lr1 = lr0 + 64;        // 64..127
    const int lk  = (tid & 3) * 4;   // 0,4,8,12

    u64 acc[8][4];
#pragma unroll
    for (int i = 0; i < 8; i++)
#pragma unroll
        for (int j = 0; j < 4; j++) acc[i][j] = 0ULL;

    for (int pass = 0; pass < 2; pass++) {
        const float* A = pass ? A2 : A1;
        const float* W = pass ? W2 : W1;
        const int K    = pass ? K2 : K1;
        if (A == nullptr) continue;

        long long a0, a1;
        if (pass == 0 && idx1) {
            a0 = (long long)idx1[bm0 + lr0] * K;
            a1 = (long long)idx1[bm0 + lr1] * K;
        } else {
            a0 = (long long)(bm0 + lr0) * K;
            a1 = (long long)(bm0 + lr1) * K;
        }
        const int  n0  = bn0 + lr0, n1 = bn0 + lr1;
        const bool nv0 = n0 < N,   nv1 = n1 < N;
        const long long w0 = (long long)n0 * K, w1 = (long long)n1 * K;

        const int nk = K >> 4;

        __syncthreads();  // protect smem reuse across passes / prior compute

        // prologue: tile 0 -> buffer 0
        float4 ra0 = *(const float4*)(A + a0 + lk);
        float4 ra1 = *(const float4*)(A + a1 + lk);
        float4 rw0 = nv0 ? *(const float4*)(W + w0 + lk) : make_float4(0.f,0.f,0.f,0.f);
        float4 rw1 = nv1 ? *(const float4*)(W + w1 + lk) : make_float4(0.f,0.f,0.f,0.f);
        As[0][lk+0][lr0] = ra0.x; As[0][lk+1][lr0] = ra0.y; As[0][lk+2][lr0] = ra0.z; As[0][lk+3][lr0] = ra0.w;
        As[0][lk+0][lr1] = ra1.x; As[0][lk+1][lr1] = ra1.y; As[0][lk+2][lr1] = ra1.z; As[0][lk+3][lr1] = ra1.w;
        Ws[0][lk+0][lr0] = rw0.x; Ws[0][lk+1][lr0] = rw0.y; Ws[0][lk+2][lr0] = rw0.z; Ws[0][lk+3][lr0] = rw0.w;
        Ws[0][lk+0][lr1] = rw1.x; Ws[0][lk+1][lr1] = rw1.y; Ws[0][lk+2][lr1] = rw1.z; Ws[0][lk+3][lr1] = rw1.w;
        __syncthreads();

        int buf = 0;
        for (int kt = 0; kt < nk; kt++) {
            const bool has_next = (kt + 1 < nk);
            if (has_next) {
                const int koff = (kt + 1) * 16 + lk;
                ra0 = *(const float4*)(A + a0 + koff);
                ra1 = *(const float4*)(A + a1 + koff);
                rw0 = nv0 ? *(const float4*)(W + w0 + koff) : make_float4(0.f,0.f,0.f,0.f);
                rw1 = nv1 ? *(const float4*)(W + w1 + koff) : make_float4(0.f,0.f,0.f,0.f);
            }
#pragma unroll
            for (int k = 0; k < 16; k++) {
                float4 af0 = *(const float4*)&As[buf][k][row0];
                float4 af1 = *(const float4*)&As[buf][k][row0 + 4];
                u64 b01 = *(const u64*)&Ws[buf][k][col0 + 0];
                u64 b23 = *(const u64*)&Ws[buf][k][col0 + 2];
                u64 b45 = *(const u64*)&Ws[buf][k][col0 + 4];
                u64 b67 = *(const u64*)&Ws[buf][k][col0 + 6];
                float av[8] = {af0.x, af0.y, af0.z, af0.w, af1.x, af1.y, af1.z, af1.w};
#pragma unroll
                for (int i = 0; i < 8; i++) {
                    u64 ai = pk2(av[i], av[i]);
                    acc[i][0] = ffma2(ai, b01, acc[i][0]);
                    acc[i][1] = ffma2(ai, b23, acc[i][1]);
                    acc[i][2] = ffma2(ai, b45, acc[i][2]);
                    acc[i][3] = ffma2(ai, b67, acc[i][3]);
                }
            }
            if (has_next) {
                const int nb = buf ^ 1;
                As[nb][lk+0][lr0] = ra0.x; As[nb][lk+1][lr0] = ra0.y; As[nb][lk+2][lr0] = ra0.z; As[nb][lk+3][lr0] = ra0.w;
                As[nb][lk+0][lr1] = ra1.x; As[nb][lk+1][lr1] = ra1.y; As[nb][lk+2][lr1] = ra1.z; As[nb][lk+3][lr1] = ra1.w;
                Ws[nb][lk+0][lr0] = rw0.x; Ws[nb][lk+1][lr0] = rw0.y; Ws[nb][lk+2][lr0] = rw0.z; Ws[nb][lk+3][lr0] = rw0.w;
                Ws[nb][lk+0][lr1] = rw1.x; Ws[nb][lk+1][lr1] = rw1.y; Ws[nb][lk+2][lr1] = rw1.z; Ws[nb][lk+3][lr1] = rw1.w;
                __syncthreads();
                buf = nb;
            }
        }
    }

    // epilogue
    const bool nvalid = (bn0 + col0) < N;   // N % 8 == 0 -> whole 8-col group
    if (nvalid) {
        float bsum[8];
#pragma unroll
        for (int j = 0; j < 8; j++) {
            const int n = bn0 + col0 + j;
            float bv = 0.f;
            if (bias1) bv += bias1[n];
            if (bias2) bv += bias2[n];
            bsum[j] = bv;
        }
#pragma unroll
        for (int i = 0; i < 8; i++) {
            float* cp = C + (long long)(bm0 + row0 + i) * N + bn0 + col0;
#pragma unroll
            for (int j = 0; j < 4; j++) {
                float2 v = up2(acc[i][j]);
                v.x += bsum[2 * j];
                v.y += bsum[2 * j + 1];
                *(float2*)(cp + 2 * j) = v;
            }
        }
    }
}

// ---------------- row-wise argmax (+ optional logsumexp -> lp) ----------------
__global__ void logits_reduce(const float* __restrict__ logits,
                              int* __restrict__ tok, float* __restrict__ lp, int want_lp)
{
    const int b = blockIdx.x;
    const float4* row = (const float4*)(logits + (long long)b * CV);
    float m = -3.4e38f; int mi = 0; float s = 0.f;
    for (int j4 = threadIdx.x; j4 < CV / 4; j4 += blockDim.x) {
        float4 v = row[j4];
        float xs[4] = {v.x, v.y, v.z, v.w};
#pragma unroll
        for (int c = 0; c < 4; c++) {
            float x = xs[c];
            if (x > m) {
                if (want_lp) s = s * expf(m - x) + 1.f;
                m = x; mi = j4 * 4 + c;
            } else if (want_lp) {
                s += expf(x - m);
            }
        }
    }
    __shared__ float sm[256], ss[256];
    __shared__ int   si[256];
    sm[threadIdx.x] = m; ss[threadIdx.x] = s; si[threadIdx.x] = mi;
    __syncthreads();
    for (int st = 128; st > 0; st >>= 1) {
        if (threadIdx.x < st) {
            float m1 = sm[threadIdx.x],      s1 = ss[threadIdx.x];      int i1 = si[threadIdx.x];
            float m2 = sm[threadIdx.x + st], s2 = ss[threadIdx.x + st]; int i2 = si[threadIdx.x + st];
            if (m2 > m1 || (m2 == m1 && i2 < i1)) {
                sm[threadIdx.x] = m2; si[threadIdx.x] = i2; ss[threadIdx.x] = s2 + s1 * expf(m1 - m2);
            } else {
                ss[threadIdx.x] = s1 + s2 * expf(m2 - m1);
            }
        }
        __syncthreads();
    }
    if (threadIdx.x == 0) {
        tok[b] = si[0];
        if (want_lp) lp[b] = -logf(ss[0]);  // chosen logit == max -> lp = -log(sum exp(x-max))
    }
}

// ---------------- LSTM cell elementwise ----------------
__global__ void lstm_cell(const float* __restrict__ gates,
                          float* __restrict__ h, float* __restrict__ c)
{
    const int t = blockIdx.x * blockDim.x + threadIdx.x;
    if (t >= CB * CH) return;
    const int b = t >> 10;        // CH = 1024
    const int j = t & 1023;
    const float* g = gates + (long long)b * (4 * CH);
    const float gi = g[j], gf = g[CH + j], gg = g[2 * CH + j], go = g[3 * CH + j];
    const float ig = 1.f / (1.f + __expf(-gi));
    const float fg = 1.f / (1.f + __expf(-gf));
    const float og = 1.f / (1.f + __expf(-go));
    const float cn = fg * c[t] + ig * tanhf(gg);
    c[t] = cn;
    h[t] = og * tanhf(cn);
}

__global__ void set_tok0(const int* __restrict__ sidx, int* __restrict__ tok)
{
    const int i = blockIdx.x * blockDim.x + threadIdx.x;
    if (i < CB) tok[i] = sidx[0];
}

// ---------------- hinge loss / accuracy row reduction ----------------
__global__ void score_rows(const float* __restrict__ ts, const float* __restrict__ ds,
                           const float* __restrict__ lp,
                           float* __restrict__ rowloss, float* __restrict__ rowcorr)
{
    const int i = blockIdx.x;
    const float* trow = ts + (long long)i * CB;
    const float* dr0 = ds + 0LL * CB * CB + (long long)i * CB;
    const float* dr1 = ds + 1LL * CB * CB + (long long)i * CB;
    const float* dr2 = ds + 2LL * CB * CB + (long long)i * CB;
    const float* dr3 = ds + 3LL * CB * CB + (long long)i * CB;

    float ls = 0.f, et = 0.f, e0 = 0.f, e1 = 0.f, e2 = 0.f, e3 = 0.f;
    for (int j = threadIdx.x; j < CB; j += 256) {
        const float t  = trow[j];
        const float a0 = dr0[j], a1 = dr1[j], a2 = dr2[j], a3 = dr3[j];
        float h = fmaxf(0.f, 1.f - t + a0) + fmaxf(0.f, 1.f - t + a1)
                + fmaxf(0.f, 1.f - t + a2) + fmaxf(0.f, 1.f - t + a3);
        ls += h * lp[j];
        et += expf(t); e0 += expf(a0); e1 += expf(a1); e2 += expf(a2); e3 += expf(a3);
    }
    __shared__ float red[6][256];
    red[0][threadIdx.x] = ls; red[1][threadIdx.x] = et;
    red[2][threadIdx.x] = e0; red[3][threadIdx.x] = e1;
    red[4][threadIdx.x] = e2; red[5][threadIdx.x] = e3;
    __syncthreads();
    for (int st = 128; st > 0; st >>= 1) {
        if (threadIdx.x < st)
#pragma unroll
            for (int q = 0; q < 6; q++) red[q][threadIdx.x] += red[q][threadIdx.x + st];
        __syncthreads();
    }
    if (threadIdx.x == 0) {
        rowloss[i] = red[0][0];
        const float tp = red[1][0] / (float)CB;
        const float mx = fmaxf(fmaxf(red[2][0], red[3][0]), fmaxf(red[4][0], red[5][0])) / (float)CB;
        rowcorr[i] = (tp >= mx) ? 1.f : 0.f;   // argmax ties -> index 0 wins
    }
}

__global__ void final_reduce(const float* __restrict__ rowloss,
                             const float* __restrict__ rowcorr, float* __restrict__ out)
{
    __shared__ float s1[256], s2[256];
    float a = 0.f, b = 0.f;
    for (int i = threadIdx.x; i < CB; i += 256) { a += rowloss[i]; b += rowcorr[i]; }
    s1[threadIdx.x] = a; s2[threadIdx.x] = b;
    __syncthreads();
    for (int st = 128; st > 0; st >>= 1) {
        if (threadIdx.x < st) { s1[threadIdx.x] += s1[threadIdx.x + st]; s2[threadIdx.x] += s2[threadIdx.x + st]; }
        __syncthreads();
    }
    if (threadIdx.x == 0) {
        out[0] = -s1[0] / (float)((long long)CB * CB);  // loss
        out[1] =  s2[0] / (float)CB;                    // accuracy
    }
}

// ---------------------------------------------------------------------------
extern "C" void kernel_launch(void* const* d_in, const int* in_sizes, int n_in,
                              void* d_out, int out_size)
{
    (void)in_sizes; (void)n_in; (void)out_size;
    const float* target   = (const float*)d_in[0];
    const float* distract = (const float*)d_in[1];
    const int*   sidx     = (const int*)d_in[2];
    // d_in[3] = max_sentence_length (compile-time CL)
    const float* emb_s   = (const float*)d_in[4];
    const float* Wih_s   = (const float*)d_in[5];
    const float* Whh_s   = (const float*)d_in[6];
    const float* bih_s   = (const float*)d_in[7];
    const float* bhh_s   = (const float*)d_in[8];
    const float* aff_s_W = (const float*)d_in[9];
    const float* aff_s_b = (const float*)d_in[10];
    const float* probs_W = (const float*)d_in[11];
    const float* probs_b = (const float*)d_in[12];
    const float* emb_r   = (const float*)d_in[13];
    const float* Wih_r   = (const float*)d_in[14];
    const float* Whh_r   = (const float*)d_in[15];
    const float* bih_r   = (const float*)d_in[16];
    const float* bhh_r   = (const float*)d_in[17];
    const float* aff_r_W = (const float*)d_in[18];
    const float* aff_r_b = (const float*)d_in[19];
    float* out = (float*)d_out;

    float *p_logits, *p_gates, *p_hs, *p_cs, *p_hr, *p_cr, *p_lp, *p_r, *p_ts, *p_ds, *p_rowloss, *p_rowcorr;
    int *p_msg, *p_tok0;
    cudaGetSymbolAddress((void**)&p_logits, g_logits);
    cudaGetSymbolAddress((void**)&p_gates, g_gates);
    cudaGetSymbolAddress((void**)&p_hs, g_hs);
    cudaGetSymbolAddress((void**)&p_cs, g_cs);
    cudaGetSymbolAddress((void**)&p_hr, g_hr);
    cudaGetSymbolAddress((void**)&p_cr, g_cr);
    cudaGetSymbolAddress((void**)&p_lp, g_lp);
    cudaGetSymbolAddress((void**)&p_r, g_r);
    cudaGetSymbolAddress((void**)&p_ts, g_ts);
    cudaGetSymbolAddress((void**)&p_ds, g_ds);
    cudaGetSymbolAddress((void**)&p_rowloss, g_rowloss);
    cudaGetSymbolAddress((void**)&p_rowcorr, g_rowcorr);
    cudaGetSymbolAddress((void**)&p_msg, g_msg);
    cudaGetSymbolAddress((void**)&p_tok0, g_tok0);

    cudaMemsetAsync(p_cs, 0, (size_t)CB * CH * sizeof(float));
    cudaMemsetAsync(p_hr, 0, (size_t)CB * CH * sizeof(float));
    cudaMemsetAsync(p_cr, 0, (size_t)CB * CH * sizeof(float));
    set_tok0<<<CB / 256, 256>>>(sidx, p_tok0);

    // h0 = target @ aff_s_W^T + aff_s_b
    sgemm_nt<<<dim3(CH / 128, CB / 128), 256>>>(CB, CH,
        target, CF, nullptr, nullptr, 0,
        aff_s_W, nullptr, aff_s_b, nullptr, p_hs);

    // ---- sender ----
    for (int t = 0; t < CL; t++) {
        const int* tokidx = (t == 0) ? p_tok0 : (p_msg + (t - 1) * CB);
        sgemm_nt<<<dim3(4 * CH / 128, CB / 128), 256>>>(CB, 4 * CH,
            emb_s, CE, tokidx, p_hs, CH,
            Wih_s, Whh_s, bih_s, bhh_s, p_gates);
        lstm_cell<<<(CB * CH) / 256, 256>>>(p_gates, p_hs, p_cs);
        sgemm_nt<<<dim3((CV + 127) / 128, CB / 128), 256>>>(CB, CV,
            p_hs, CH, nullptr, nullptr, 0,
            probs_W, nullptr, probs_b, nullptr, p_logits);
        logits_reduce<<<CB, 256>>>(p_logits, p_msg + t * CB, p_lp, (t == CL - 1) ? 1 : 0);
    }

    // ---- receiver ----
    for (int t = 0; t < CL; t++) {
        sgemm_nt<<<dim3(4 * CH / 128, CB / 128), 256>>>(CB, 4 * CH,
            emb_r, CE, p_msg + t * CB, p_hr, CH,
            Wih_r, Whh_r, bih_r, bhh_r, p_gates);
        lstm_cell<<<(CB * CH) / 256, 256>>>(p_gates, p_hr, p_cr);
    }

    // r = hr @ aff_r_W^T + aff_r_b
    sgemm_nt<<<dim3(CF / 128, CB / 128), 256>>>(CB, CF,
        p_hr, CH, nullptr, nullptr, 0,
        aff_r_W, nullptr, aff_r_b, nullptr, p_r);

    // ts = target @ r^T ; ds[d] = distractors[d] @ r^T
    sgemm_nt<<<dim3(CB / 128, CB / 128), 256>>>(CB, CB,
        target, CF, nullptr, nullptr, 0,
        p_r, nullptr, nullptr, nullptr, p_ts);
    sgemm_nt<<<dim3(CB / 128, (CD * CB) / 128), 256>>>(CD * CB, CB,
        distract, CF, nullptr, nullptr, 0,
        p_r, nullptr, nullptr, nullptr, p_ds);

    score_rows<<<CB, 256>>>(p_ts, p_ds, p_lp, p_rowloss, p_rowcorr);
    final_reduce<<<1, 256>>>(p_rowloss, p_rowcorr, out);
}

// round 4
// speedup vs baseline: 1.1154x; 1.1154x over previous
#include <cuda_runtime.h>
#include <cstdint>

typedef unsigned long long u64;
typedef uint32_t u32;

constexpr int CB = 1024;   // batch
constexpr int CF = 4096;   // feature
constexpr int CV = 20000;  // vocab
constexpr int CE = 512;    // embed dim
constexpr int CH = 1024;   // hidden
constexpr int CL = 20;     // sentence length
constexpr int CD = 4;      // distractors

// ---------------- GEMM tiling ----------------
constexpr int BM = 128, BN = 256, BK = 16;
constexpr int APAD = 20;                    // smem row stride (floats) -> conflict-free frags
constexpr int A_FL = BM * APAD;             // 2560 floats / stage
constexpr int B_FL = BN * APAD;             // 5120 floats / stage

// ---------------- scratch (static device globals; no allocation) ----------------
#define DG __device__ __align__(256)
DG float g_logits[(size_t)CB * CV];
DG float g_gates[(size_t)CB * 4 * CH];
DG float g_hs[CB * CH];
DG float g_cs[CB * CH];
DG float g_hr[CB * CH];
DG float g_cr[CB * CH];
DG float g_x[CB * CE];
DG float g_lp[CB];
DG float g_r[(size_t)CB * CF];
DG float g_ts[(size_t)CB * CB];
DG float g_ds[(size_t)CD * CB * CB];
DG float g_rowloss[CB];
DG float g_rowcorr[CB];
DG int   g_msg[CL * CB];
DG int   g_tok0[CB];

// ---------------- low-level helpers ----------------
__device__ __forceinline__ u32 s2u(const void* p) {
    u32 a; asm("{ .reg .u64 t; cvta.to.shared.u64 t, %1; cvt.u32.u64 %0, t; }" : "=r"(a) : "l"(p));
    return a;
}
__device__ __forceinline__ u32 tf32hi(float x) {
    u32 r; asm("cvt.rna.tf32.f32 %0, %1;" : "=r"(r) : "f"(x)); return r;
}
__device__ __forceinline__ void cp8(u32 dst, const void* src, bool v) {
    int sz = v ? 8 : 0;
    asm volatile("cp.async.ca.shared.global [%0], [%1], 8, %2;" :: "r"(dst), "l"(src), "r"(sz) : "memory");
}
#define CP_COMMIT() asm volatile("cp.async.commit_group;" ::: "memory")

__device__ __forceinline__ void mma8(float* d, const u32* a, const u32* b) {
    asm volatile(
        "mma.sync.aligned.m16n8k8.row.col.f32.tf32.tf32.f32 "
        "{%0,%1,%2,%3}, {%4,%5,%6,%7}, {%8,%9}, {%0,%1,%2,%3};"
        : "+f"(d[0]), "+f"(d[1]), "+f"(d[2]), "+f"(d[3])
        : "r"(a[0]), "r"(a[1]), "r"(a[2]), "r"(a[3]), "r"(b[0]), "r"(b[1]));
}

// ---------------------------------------------------------------------------
// NT GEMM, 3xTF32 via mma.sync:
// C[M,N] = A1[M,K1]*B1[N,K1]^T (+ A2[M,K2]*B2[N,K2]^T) + bias1 + bias2
// fp32 inputs (K-major both sides); hi/lo tf32 split done in registers.
// M % 128 == 0, K % 16 == 0, N % 8 == 0 (N-edge guarded).
// ---------------------------------------------------------------------------
__global__ __launch_bounds__(256, 1)
void tmma_nt(int M, int N,
             const float* __restrict__ A1, int K1,
             const float* __restrict__ A2, int K2,
             const float* __restrict__ B1, const float* __restrict__ B2,
             const float* __restrict__ bias1, const float* __restrict__ bias2,
             float* __restrict__ C)
{
    __shared__ float sm[2 * (A_FL + B_FL)];   // 60 KB static
    float* sA = sm;                    // [2][BM][APAD]
    float* sB = sm + 2 * A_FL;         // [2][BN][APAD]

    const int tid  = threadIdx.x;
    const int wid  = tid >> 5;
    const int lane = tid & 31;
    const int g    = lane >> 2;        // 0..7
    const int t    = lane & 3;         // 0..3
    const int wm   = (wid & 1) * 64;
    const int wn   = (wid >> 1) * 64;
    const int bn0  = blockIdx.x * BN;
    const int bm0  = blockIdx.y * BM;

    const int nk1 = K1 / BK;
    const int nk2 = A2 ? (K2 / BK) : 0;
    const int nkt = nk1 + nk2;

    auto load_stage = [&](int gkt, int stage) {
        const float *A, *B; int K, kt;
        if (gkt < nk1) { A = A1; B = B1; K = K1; kt = gkt; }
        else           { A = A2; B = B2; K = K2; kt = gkt - nk1; }
        const int koff = kt * BK;
        u32 sa = s2u(sA + stage * A_FL);
        u32 sb = s2u(sB + stage * B_FL);
        // A: 128 rows x 8 chunks of 8B
#pragma unroll
        for (int it = 0; it < 4; it++) {
            int c = tid + it * 256;
            int m = c >> 3, ch = c & 7;
            cp8(sa + (m * APAD + ch * 2) * 4,
                A + (size_t)(bm0 + m) * K + koff + ch * 2, true);
        }
        // B: 256 rows x 8 chunks
#pragma unroll
        for (int it = 0; it < 8; it++) {
            int c = tid + it * 256;
            int n = c >> 3, ch = c & 7;
            bool v = (bn0 + n) < N;
            const float* src = B + (size_t)(v ? (bn0 + n) : 0) * K + koff + ch * 2;
            cp8(sb + (n * APAD + ch * 2) * 4, src, v);
        }
        CP_COMMIT();
    };

    float d[4][8][4];
#pragma unroll
    for (int i = 0; i < 4; i++)
#pragma unroll
        for (int j = 0; j < 8; j++)
#pragma unroll
            for (int q = 0; q < 4; q++) d[i][j][q] = 0.f;

    load_stage(0, 0);

    for (int s = 0; s < nkt; s++) {
        if (s + 1 < nkt) {
            load_stage(s + 1, (s + 1) & 1);
            asm volatile("cp.async.wait_group 1;" ::: "memory");
        } else {
            asm volatile("cp.async.wait_group 0;" ::: "memory");
        }
        __syncthreads();

        const float* ap = sA + (s & 1) * A_FL + (wm + g) * APAD + t;
        const float* bp = sB + (s & 1) * B_FL + (wn + g) * APAD + t;

#pragma unroll
        for (int kk = 0; kk < BK; kk += 8) {
            u32 bh[8][2], bl[8][2];
#pragma unroll
            for (int nt = 0; nt < 8; nt++) {
#pragma unroll
                for (int r = 0; r < 2; r++) {
                    float x = bp[nt * 8 * APAD + r * 4 + kk];
                    u32 h = tf32hi(x);
                    bh[nt][r] = h;
                    bl[nt][r] = tf32hi(x - __uint_as_float(h));
                }
            }
#pragma unroll
            for (int mt = 0; mt < 4; mt++) {
                u32 ah[4], al[4];
#pragma unroll
                for (int rg = 0; rg < 4; rg++) {
                    float x = ap[mt * 16 * APAD + (rg & 1) * 8 * APAD + (rg >> 1) * 4 + kk];
                    u32 h = tf32hi(x);
                    ah[rg] = h;
                    al[rg] = tf32hi(x - __uint_as_float(h));
                }
#pragma unroll
                for (int nt = 0; nt < 8; nt++) {
                    mma8(d[mt][nt], ah, bh[nt]);
                    mma8(d[mt][nt], ah, bl[nt]);
                    mma8(d[mt][nt], al, bh[nt]);
                }
            }
        }
        __syncthreads();
    }

    // epilogue: c0,c1 -> (row, 2t..2t+1); c2,c3 -> (row+8, ...)
#pragma unroll
    for (int nt = 0; nt < 8; nt++) {
        const int cb = bn0 + wn + nt * 8;
        if (cb >= N) continue;
        const int col = cb + 2 * t;
        float b0 = 0.f, b1 = 0.f;
        if (bias1) { b0 += bias1[col]; b1 += bias1[col + 1]; }
        if (bias2) { b0 += bias2[col]; b1 += bias2[col + 1]; }
#pragma unroll
        for (int mt = 0; mt < 4; mt++) {
            const int row = bm0 + wm + mt * 16 + g;
            float2 v0 = make_float2(d[mt][nt][0] + b0, d[mt][nt][1] + b1);
            float2 v1 = make_float2(d[mt][nt][2] + b0, d[mt][nt][3] + b1);
            *(float2*)(C + (size_t)row * N + col) = v0;
            *(float2*)(C + (size_t)(row + 8) * N + col) = v1;
        }
    }
}

// ---------------- elementwise kernels ----------------
__global__ void gather_k(const int* __restrict__ tok, const float* __restrict__ emb,
                         float* __restrict__ x)
{
    int i = blockIdx.x * blockDim.x + threadIdx.x;      // over CB * CE/4
    if (i >= CB * (CE / 4)) return;
    int b = i / (CE / 4), j = (i % (CE / 4)) * 4;
    float4 e = *(const float4*)(emb + (size_t)tok[b] * CE + j);
    *(float4*)(x + (size_t)b * CE + j) = e;
}

__global__ void lstm_cell(const float* __restrict__ gates,
                          float* __restrict__ h, float* __restrict__ c)
{
    const int t = blockIdx.x * blockDim.x + threadIdx.x;
    if (t >= CB * CH) return;
    const int b = t >> 10, j = t & 1023;
    const float* g = gates + (size_t)b * (4 * CH);
    const float gi = g[j], gf = g[CH + j], gg = g[2 * CH + j], go = g[3 * CH + j];
    const float ig = 1.f / (1.f + __expf(-gi));
    const float fg = 1.f / (1.f + __expf(-gf));
    const float og = 1.f / (1.f + __expf(-go));
    const float cn = fg * c[t] + ig * tanhf(gg);
    c[t] = cn;
    h[t] = og * tanhf(cn);
}

__global__ void set_tok0(const int* __restrict__ sidx, int* __restrict__ tok)
{
    const int i = blockIdx.x * blockDim.x + threadIdx.x;
    if (i < CB) tok[i] = sidx[0];
}

// ---------------- row-wise argmax (+ optional logsumexp -> lp) ----------------
__global__ void logits_reduce(const float* __restrict__ logits,
                              int* __restrict__ tok, float* __restrict__ lp, int want_lp)
{
    const int b = blockIdx.x;
    const float4* row = (const float4*)(logits + (size_t)b * CV);
    float m = -3.4e38f; int mi = 0; float s = 0.f;
    for (int j4 = threadIdx.x; j4 < CV / 4; j4 += blockDim.x) {
        float4 v = row[j4];
        float xs[4] = {v.x, v.y, v.z, v.w};
#pragma unroll
        for (int c = 0; c < 4; c++) {
            float x = xs[c];
            if (x > m) {
                if (want_lp) s = s * expf(m - x) + 1.f;
                m = x; mi = j4 * 4 + c;
            } else if (want_lp) {
                s += expf(x - m);
            }
        }
    }
    __shared__ float sm[256], ss[256];
    __shared__ int   si[256];
    sm[threadIdx.x] = m; ss[threadIdx.x] = s; si[threadIdx.x] = mi;
    __syncthreads();
    for (int st = 128; st > 0; st >>= 1) {
        if (threadIdx.x < st) {
            float m1 = sm[threadIdx.x],      s1 = ss[threadIdx.x];      int i1 = si[threadIdx.x];
            float m2 = sm[threadIdx.x + st], s2 = ss[threadIdx.x + st]; int i2 = si[threadIdx.x + st];
            if (m2 > m1 || (m2 == m1 && i2 < i1)) {
                sm[threadIdx.x] = m2; si[threadIdx.x] = i2; ss[threadIdx.x] = s2 + s1 * expf(m1 - m2);
            } else {
                ss[threadIdx.x] = s1 + s2 * expf(m2 - m1);
            }
        }
        __syncthreads();
    }
    if (threadIdx.x == 0) {
        tok[b] = si[0];
        if (want_lp) lp[b] = -logf(ss[0]);
    }
}

// ---------------- hinge loss / accuracy reductions ----------------
__global__ void score_rows(const float* __restrict__ ts, const float* __restrict__ ds,
                           const float* __restrict__ lp,
                           float* __restrict__ rowloss, float* __restrict__ rowcorr)
{
    const int i = blockIdx.x;
    const float* trow = ts + (size_t)i * CB;
    const float* dr0 = ds + 0ULL * CB * CB + (size_t)i * CB;
    const float* dr1 = ds + 1ULL * CB * CB + (size_t)i * CB;
    const float* dr2 = ds + 2ULL * CB * CB + (size_t)i * CB;
    const float* dr3 = ds + 3ULL * CB * CB + (size_t)i * CB;

    float ls = 0.f, et = 0.f, e0 = 0.f, e1 = 0.f, e2 = 0.f, e3 = 0.f;
    for (int j = threadIdx.x; j < CB; j += 256) {
        const float t  = trow[j];
        const float a0 = dr0[j], a1 = dr1[j], a2 = dr2[j], a3 = dr3[j];
        float h = fmaxf(0.f, 1.f - t + a0) + fmaxf(0.f, 1.f - t + a1)
                + fmaxf(0.f, 1.f - t + a2) + fmaxf(0.f, 1.f - t + a3);
        ls += h * lp[j];
        et += expf(t); e0 += expf(a0); e1 += expf(a1); e2 += expf(a2); e3 += expf(a3);
    }
    __shared__ float red[6][256];
    red[0][threadIdx.x] = ls; red[1][threadIdx.x] = et;
    red[2][threadIdx.x] = e0; red[3][threadIdx.x] = e1;
    red[4][threadIdx.x] = e2; red[5][threadIdx.x] = e3;
    __syncthreads();
    for (int st = 128; st > 0; st >>= 1) {
        if (threadIdx.x < st)
#pragma unroll
            for (int q = 0; q < 6; q++) red[q][threadIdx.x] += red[q][threadIdx.x + st];
        __syncthreads();
    }
    if (threadIdx.x == 0) {
        rowloss[i] = red[0][0];
        const float tp = red[1][0] / (float)CB;
        const float mx = fmaxf(fmaxf(red[2][0], red[3][0]), fmaxf(red[4][0], red[5][0])) / (float)CB;
        rowcorr[i] = (tp >= mx) ? 1.f : 0.f;
    }
}

__global__ void final_reduce(const float* __restrict__ rowloss,
                             const float* __restrict__ rowcorr, float* __restrict__ out)
{
    __shared__ float s1[256], s2[256];
    float a = 0.f, b = 0.f;
    for (int i = threadIdx.x; i < CB; i += 256) { a += rowloss[i]; b += rowcorr[i]; }
    s1[threadIdx.x] = a; s2[threadIdx.x] = b;
    __syncthreads();
    for (int st = 128; st > 0; st >>= 1) {
        if (threadIdx.x < st) { s1[threadIdx.x] += s1[threadIdx.x + st]; s2[threadIdx.x] += s2[threadIdx.x + st]; }
        __syncthreads();
    }
    if (threadIdx.x == 0) {
        out[0] = -s1[0] / (float)((size_t)CB * CB);
        out[1] =  s2[0] / (float)CB;
    }
}

// ---------------------------------------------------------------------------
extern "C" void kernel_launch(void* const* d_in, const int* in_sizes, int n_in,
                              void* d_out, int out_size)
{
    (void)in_sizes; (void)n_in; (void)out_size;
    const float* target   = (const float*)d_in[0];
    const float* distract = (const float*)d_in[1];
    const int*   sidx     = (const int*)d_in[2];
    const float* emb_s   = (const float*)d_in[4];
    const float* Wih_s   = (const float*)d_in[5];
    const float* Whh_s   = (const float*)d_in[6];
    const float* bih_s   = (const float*)d_in[7];
    const float* bhh_s   = (const float*)d_in[8];
    const float* aff_s_W = (const float*)d_in[9];
    const float* aff_s_b = (const float*)d_in[10];
    const float* probs_W = (const float*)d_in[11];
    const float* probs_b = (const float*)d_in[12];
    const float* emb_r   = (const float*)d_in[13];
    const float* Wih_r   = (const float*)d_in[14];
    const float* Whh_r   = (const float*)d_in[15];
    const float* bih_r   = (const float*)d_in[16];
    const float* bhh_r   = (const float*)d_in[17];
    const float* aff_r_W = (const float*)d_in[18];
    const float* aff_r_b = (const float*)d_in[19];
    float* out = (float*)d_out;

#define SYM(p, s) float* p; cudaGetSymbolAddress((void**)&p, s)
    SYM(p_logits, g_logits); SYM(p_gates, g_gates);
    SYM(p_hs, g_hs); SYM(p_cs, g_cs); SYM(p_hr, g_hr); SYM(p_cr, g_cr);
    SYM(p_x, g_x);
    SYM(p_lp, g_lp); SYM(p_r, g_r); SYM(p_ts, g_ts); SYM(p_ds, g_ds);
    SYM(p_rowloss, g_rowloss); SYM(p_rowcorr, g_rowcorr);
#undef SYM
    int *p_msg, *p_tok0;
    cudaGetSymbolAddress((void**)&p_msg, g_msg);
    cudaGetSymbolAddress((void**)&p_tok0, g_tok0);

    cudaMemsetAsync(p_cs, 0, (size_t)CB * CH * sizeof(float));
    cudaMemsetAsync(p_hr, 0, (size_t)CB * CH * sizeof(float));
    cudaMemsetAsync(p_cr, 0, (size_t)CB * CH * sizeof(float));
    set_tok0<<<CB / 256, 256>>>(sidx, p_tok0);

    // h0 = target @ aff_s_W^T + aff_s_b
    tmma_nt<<<dim3(CH / BN, CB / BM), 256>>>(CB, CH,
        target, CF, nullptr, 0, aff_s_W, nullptr, aff_s_b, nullptr, p_hs);

    // ---- sender ----
    for (int t = 0; t < CL; t++) {
        const int* tokidx = (t == 0) ? p_tok0 : (p_msg + (t - 1) * CB);
        gather_k<<<(CB * CE / 4 + 255) / 256, 256>>>(tokidx, emb_s, p_x);
        tmma_nt<<<dim3(4 * CH / BN, CB / BM), 256>>>(CB, 4 * CH,
            p_x, CE, p_hs, CH, Wih_s, Whh_s, bih_s, bhh_s, p_gates);
        lstm_cell<<<(CB * CH) / 256, 256>>>(p_gates, p_hs, p_cs);
        tmma_nt<<<dim3((CV + BN - 1) / BN, CB / BM), 256>>>(CB, CV,
            p_hs, CH, nullptr, 0, probs_W, nullptr, probs_b, nullptr, p_logits);
        logits_reduce<<<CB, 256>>>(p_logits, p_msg + t * CB, p_lp, (t == CL - 1) ? 1 : 0);
    }

    // ---- receiver ----
    for (int t = 0; t < CL; t++) {
        gather_k<<<(CB * CE / 4 + 255) / 256, 256>>>(p_msg + t * CB, emb_r, p_x);
        tmma_nt<<<dim3(4 * CH / BN, CB / BM), 256>>>(CB, 4 * CH,
            p_x, CE, p_hr, CH, Wih_r, Whh_r, bih_r, bhh_r, p_gates);
        lstm_cell<<<(CB * CH) / 256, 256>>>(p_gates, p_hr, p_cr);
    }

    // r = hr @ aff_r_W^T + aff_r_b
    tmma_nt<<<dim3(CF / BN, CB / BM), 256>>>(CB, CF,
        p_hr, CH, nullptr, 0, aff_r_W, nullptr, aff_r_b, nullptr, p_r);

    // ts = target @ r^T ; ds = distractors @ r^T
    tmma_nt<<<dim3(CB / BN, CB / BM), 256>>>(CB, CB,
        target, CF, nullptr, 0, p_r, nullptr, nullptr, nullptr, p_ts);
    tmma_nt<<<dim3(CB / BN, (CD * CB) / BM), 256>>>(CD * CB, CB,
        distract, CF, nullptr, 0, p_r, nullptr, nullptr, nullptr, p_ds);

    score_rows<<<CB, 256>>>(p_ts, p_ds, p_lp, p_rowloss, p_rowcorr);
    final_reduce<<<1, 256>>>(p_rowloss, p_rowcorr, out);
}

// round 5
// speedup vs baseline: 1.5958x; 1.4307x over previous
#include <cuda_runtime.h>
#include <cstdint>

typedef unsigned long long u64;
typedef uint32_t u32;

constexpr int CB = 1024;   // batch
constexpr int CF = 4096;   // feature
constexpr int CV = 20000;  // vocab
constexpr int CE = 512;    // embed dim
constexpr int CH = 1024;   // hidden
constexpr int CL = 20;     // sentence length
constexpr int CD = 4;      // distractors

// ---------------- GEMM tiling ----------------
constexpr int BM = 128, BN = 128, BK = 16;
constexpr int APAD = 20;                 // row stride (floats) -> conflict-free frag LDS
constexpr int TFL = BM * APAD;           // 2560 floats per plane tile
constexpr int SMEM_BYTES = 2 /*stages*/ * 4 /*planes Ah,Al,Bh,Bl*/ * TFL * 4;  // 81920

// ---------------- scratch (static device globals; no allocation) ----------------
#define DG __device__ __align__(256)
// tf32 hi/lo planes
DG float g_pw_h[(size_t)CV * CH];    DG float g_pw_l[(size_t)CV * CH];
DG float g_wihs_h[4 * CH * CE];      DG float g_wihs_l[4 * CH * CE];
DG float g_whhs_h[4 * CH * CH];      DG float g_whhs_l[4 * CH * CH];
DG float g_wihr_h[4 * CH * CE];      DG float g_wihr_l[4 * CH * CE];
DG float g_whhr_h[4 * CH * CH];      DG float g_whhr_l[4 * CH * CH];
DG float g_affs_h[CH * CF];          DG float g_affs_l[CH * CF];
DG float g_affr_h[CF * CH];          DG float g_affr_l[CF * CH];
DG float g_tgt_h[(size_t)CB * CF];   DG float g_tgt_l[(size_t)CB * CF];
DG float g_dst_h[(size_t)CD * CB * CF]; DG float g_dst_l[(size_t)CD * CB * CF];
DG float g_r_h[(size_t)CB * CF];     DG float g_r_l[(size_t)CB * CF];
DG float g_hs_h[CB * CH];            DG float g_hs_l[CB * CH];
DG float g_hr_h[CB * CH];            DG float g_hr_l[CB * CH];
DG float g_x_h[CB * CE];             DG float g_x_l[CB * CE];
// raw buffers
DG float g_logits[(size_t)CB * CV];
DG float g_gates[(size_t)CB * 4 * CH];
DG float g_hs[CB * CH];              // raw fp32 sender h (for exact rescue dots)
DG float g_hr[CB * CH];
DG float g_cs[CB * CH];
DG float g_cr[CB * CH];
DG float g_lp[CB];
DG float g_r[(size_t)CB * CF];
DG float g_ts[(size_t)CB * CB];
DG float g_ds[(size_t)CD * CB * CB];
DG float g_rowloss[CB];
DG float g_rowcorr[CB];
DG float g_wmax2[1];
DG int   g_msg[CL * CB];
DG int   g_tok0[CB];

// ---------------- low-level helpers ----------------
__device__ __forceinline__ u32 s2u(const void* p) {
    u32 a; asm("{ .reg .u64 t; cvta.to.shared.u64 t, %1; cvt.u32.u64 %0, t; }" : "=r"(a) : "l"(p));
    return a;
}
__device__ __forceinline__ float tf32r(float x) {
    float r; asm("cvt.rna.tf32.f32 %0, %1;" : "=f"(r) : "f"(x)); return r;
}
__device__ __forceinline__ void cp8(u32 dst, const void* src, bool v) {
    int sz = v ? 8 : 0;
    asm volatile("cp.async.ca.shared.global [%0], [%1], 8, %2;" :: "r"(dst), "l"(src), "r"(sz) : "memory");
}
#define CP_COMMIT() asm volatile("cp.async.commit_group;" ::: "memory")

__device__ __forceinline__ void mma8(float* d, const u32* a, const u32* b) {
    asm volatile(
        "mma.sync.aligned.m16n8k8.row.col.f32.tf32.tf32.f32 "
        "{%0,%1,%2,%3}, {%4,%5,%6,%7}, {%8,%9}, {%0,%1,%2,%3};"
        : "+f"(d[0]), "+f"(d[1]), "+f"(d[2]), "+f"(d[3])
        : "r"(a[0]), "r"(a[1]), "r"(a[2]), "r"(a[3]), "r"(b[0]), "r"(b[1]));
}

// ---------------------------------------------------------------------------
// NT GEMM on pre-split tf32 planes.
// NPASS=3: C = Ah*Bh + Ah*Bl + Al*Bh (full split precision, err ~2^-22)
// NPASS=1: C = Ah*Bh (single tf32, err ~2^-10 * ||h||*||w||)
// C[M,N] (+bias1+bias2), optional second A-pass (A2/B2 planes, K2).
// M%128==0, K%16==0, N%8==0 (N edge guarded).
// ---------------------------------------------------------------------------
template<int NPASS>
__global__ __launch_bounds__(256, 2)
void tmma_nt(int M, int N,
             const float* __restrict__ A1h, const float* __restrict__ A1l, int K1,
             const float* __restrict__ A2h, const float* __restrict__ A2l, int K2,
             const float* __restrict__ B1h, const float* __restrict__ B1l,
             const float* __restrict__ B2h, const float* __restrict__ B2l,
             const float* __restrict__ bias1, const float* __restrict__ bias2,
             float* __restrict__ C)
{
    extern __shared__ float sm[];   // [stage][plane: Ah,Al,Bh,Bl][TFL]

    const int tid  = threadIdx.x;
    const int wid  = tid >> 5;
    const int lane = tid & 31;
    const int g    = lane >> 2;
    const int t    = lane & 3;
    const int wm   = (wid & 3) * 32;    // 4 M-warps
    const int wn   = (wid >> 2) * 64;   // 2 N-warps
    const int bn0  = blockIdx.x * BN;
    const int bm0  = blockIdx.y * BM;

    const int nk1 = K1 / BK;
    const int nk2 = A2h ? (K2 / BK) : 0;
    const int nkt = nk1 + nk2;

    auto load_stage = [&](int gkt, int stage) {
        const float *Ah, *Al, *Bh, *Bl; int K, kt;
        if (gkt < nk1) { Ah = A1h; Al = A1l; Bh = B1h; Bl = B1l; K = K1; kt = gkt; }
        else           { Ah = A2h; Al = A2l; Bh = B2h; Bl = B2l; K = K2; kt = gkt - nk1; }
        const int koff = kt * BK;
        float* st = sm + stage * 4 * TFL;
        u32 uah = s2u(st), ual = s2u(st + TFL), ubh = s2u(st + 2 * TFL), ubl = s2u(st + 3 * TFL);
#pragma unroll
        for (int it = 0; it < 4; it++) {
            int c = tid + it * 256;
            int row = c >> 3, ch = c & 7;
            u32 off = (row * APAD + ch * 2) * 4;
            // A rows always valid
            const size_t ga = (size_t)(bm0 + row) * K + koff + ch * 2;
            cp8(uah + off, Ah + ga, true);
            if (NPASS == 3) cp8(ual + off, Al + ga, true);
            // B rows guarded (zero-fill OOB)
            bool v = (bn0 + row) < N;
            const size_t gb = (size_t)(v ? (bn0 + row) : 0) * K + koff + ch * 2;
            cp8(ubh + off, Bh + gb, v);
            if (NPASS == 3) cp8(ubl + off, Bl + gb, v);
        }
        CP_COMMIT();
    };

    float d[2][8][4];
#pragma unroll
    for (int i = 0; i < 2; i++)
#pragma unroll
        for (int j = 0; j < 8; j++)
#pragma unroll
            for (int q = 0; q < 4; q++) d[i][j][q] = 0.f;

    load_stage(0, 0);

    for (int s = 0; s < nkt; s++) {
        if (s + 1 < nkt) {
            load_stage(s + 1, (s + 1) & 1);
            asm volatile("cp.async.wait_group 1;" ::: "memory");
        } else {
            asm volatile("cp.async.wait_group 0;" ::: "memory");
        }
        __syncthreads();

        const float* st = sm + (s & 1) * 4 * TFL;
        const float* aph = st + (wm + g) * APAD + t;
        const float* apl = aph + TFL;
        const float* bph = st + 2 * TFL + (wn + g) * APAD + t;
        const float* bpl = bph + TFL;

#pragma unroll
        for (int kk = 0; kk < BK; kk += 8) {
            u32 ah[2][4], al[2][4];
#pragma unroll
            for (int mt = 0; mt < 2; mt++) {
#pragma unroll
                for (int rg = 0; rg < 4; rg++) {
                    const int idx = mt * 16 * APAD + (rg & 1) * 8 * APAD + (rg >> 1) * 4 + kk;
                    ah[mt][rg] = __float_as_uint(aph[idx]);
                    if (NPASS == 3) al[mt][rg] = __float_as_uint(apl[idx]);
                }
            }
#pragma unroll
            for (int nt = 0; nt < 8; nt++) {
                u32 bh[2], bl[2];
#pragma unroll
                for (int r = 0; r < 2; r++) {
                    const int idx = nt * 8 * APAD + r * 4 + kk;
                    bh[r] = __float_as_uint(bph[idx]);
                    if (NPASS == 3) bl[r] = __float_as_uint(bpl[idx]);
                }
#pragma unroll
                for (int mt = 0; mt < 2; mt++) {
                    mma8(d[mt][nt], ah[mt], bh);
                    if (NPASS == 3) {
                        mma8(d[mt][nt], ah[mt], bl);
                        mma8(d[mt][nt], al[mt], bh);
                    }
                }
            }
        }
        __syncthreads();
    }

    // epilogue
#pragma unroll
    for (int nt = 0; nt < 8; nt++) {
        const int cb = bn0 + wn + nt * 8;
        if (cb >= N) continue;
        const int col = cb + 2 * t;
        float b0 = 0.f, b1 = 0.f;
        if (bias1) { b0 += bias1[col]; b1 += bias1[col + 1]; }
        if (bias2) { b0 += bias2[col]; b1 += bias2[col + 1]; }
#pragma unroll
        for (int mt = 0; mt < 2; mt++) {
            const int row = bm0 + wm + mt * 16 + g;
            float2 v0 = make_float2(d[mt][nt][0] + b0, d[mt][nt][1] + b1);
            float2 v1 = make_float2(d[mt][nt][2] + b0, d[mt][nt][3] + b1);
            *(float2*)(C + (size_t)row * N + col) = v0;
            *(float2*)(C + (size_t)(row + 8) * N + col) = v1;
        }
    }
}

// ---------------- split / gather / lstm elementwise ----------------
__global__ void split_k(const float4* __restrict__ src, float4* __restrict__ hi,
                        float4* __restrict__ lo, int n4)
{
    int i = blockIdx.x * blockDim.x + threadIdx.x;
    if (i >= n4) return;
    float4 s = src[i];
    float4 h, l;
    h.x = tf32r(s.x); l.x = tf32r(s.x - h.x);
    h.y = tf32r(s.y); l.y = tf32r(s.y - h.y);
    h.z = tf32r(s.z); l.z = tf32r(s.z - h.z);
    h.w = tf32r(s.w); l.w = tf32r(s.w - h.w);
    hi[i] = h; lo[i] = l;
}

__global__ void gather_split_k(const int* __restrict__ tok, const float* __restrict__ emb,
                               float* __restrict__ xh, float* __restrict__ xl)
{
    int i = blockIdx.x * blockDim.x + threadIdx.x;
    if (i >= CB * (CE / 4)) return;
    int b = i / (CE / 4), j = (i % (CE / 4)) * 4;
    float4 e = *(const float4*)(emb + (size_t)tok[b] * CE + j);
    float4 h, l;
    h.x = tf32r(e.x); l.x = tf32r(e.x - h.x);
    h.y = tf32r(e.y); l.y = tf32r(e.y - h.y);
    h.z = tf32r(e.z); l.z = tf32r(e.z - h.z);
    h.w = tf32r(e.w); l.w = tf32r(e.w - h.w);
    *(float4*)(xh + (size_t)b * CE + j) = h;
    *(float4*)(xl + (size_t)b * CE + j) = l;
}

__global__ void lstm_cell_split(const float* __restrict__ gates, float* __restrict__ c,
                                float* __restrict__ hraw,
                                float* __restrict__ hhi, float* __restrict__ hlo)
{
    const int t = blockIdx.x * blockDim.x + threadIdx.x;
    if (t >= CB * CH) return;
    const int b = t >> 10, j = t & 1023;
    const float* g = gates + (size_t)b * (4 * CH);
    const float gi = g[j], gf = g[CH + j], gg = g[2 * CH + j], go = g[3 * CH + j];
    const float ig = 1.f / (1.f + __expf(-gi));
    const float fg = 1.f / (1.f + __expf(-gf));
    const float og = 1.f / (1.f + __expf(-go));
    const float cn = fg * c[t] + ig * tanhf(gg);
    c[t] = cn;
    const float h = og * tanhf(cn);
    hraw[t] = h;
    const float hh = tf32r(h);
    hhi[t] = hh;
    hlo[t] = tf32r(h - hh);
}

__global__ void set_tok0(const int* __restrict__ sidx, int* __restrict__ tok)
{
    const int i = blockIdx.x * blockDim.x + threadIdx.x;
    if (i < CB) tok[i] = sidx[0];
}

// max squared row-norm of probs_W (one warp per vocab row)
__global__ void wnorms_max(const float* __restrict__ W, float* __restrict__ wmax2)
{
    const int row = blockIdx.x * 8 + (threadIdx.x >> 5);
    const int lane = threadIdx.x & 31;
    if (row >= CV) return;
    const float* w = W + (size_t)row * CH;
    float s = 0.f;
    for (int k = lane; k < CH; k += 32) { float v = w[k]; s += v * v; }
#pragma unroll
    for (int st = 16; st > 0; st >>= 1) s += __shfl_xor_sync(0xffffffff, s, st);
    if (lane == 0) atomicMax((int*)wmax2, __float_as_int(s));   // s >= 0
}

// ---------------------------------------------------------------------------
// argmax over tf32 phase-1 logits + exact fp32 rescue of near-max candidates.
// Sound: tf32 logit error <= 2^-10*||h||*||w_v|| ; candidates = cols within
// 4x that bound (margin 2^-8*||h||*wmax) of the observed max.
// ---------------------------------------------------------------------------
__global__ void logits_argmax(const float* __restrict__ logits,
                              const float* __restrict__ h,
                              const float* __restrict__ W,
                              const float* __restrict__ pb,
                              const float* __restrict__ wmax2,
                              int* __restrict__ tok, float* __restrict__ lp, int want_lp)
{
    const int b = blockIdx.x;
    const int tid = threadIdx.x;
    __shared__ float sh[CH];
    __shared__ float smx[256], ssm[256];
    __shared__ int   sidx[256];

    // load h row, accumulate norm^2
    float nrm = 0.f;
    for (int i = tid; i < CH; i += 256) { float v = h[(size_t)b * CH + i]; sh[i] = v; nrm += v * v; }
    smx[tid] = nrm;
    __syncthreads();
    for (int st = 128; st > 0; st >>= 1) {
        if (tid < st) smx[tid] += smx[tid + st];
        __syncthreads();
    }
    const float hn2 = smx[0];
    __syncthreads();

    // phase 1: max (+ optional online logsumexp)
    const float* row = logits + (size_t)b * CV;
    float m = -3.4e38f, s = 0.f;
    for (int j = tid; j < CV; j += 256) {
        float x = row[j];
        if (x > m) {
            if (want_lp) s = s * expf(m - x) + 1.f;
            m = x;
        } else if (want_lp) {
            s += expf(x - m);
        }
    }
    smx[tid] = m; ssm[tid] = s;
    __syncthreads();
    for (int st = 128; st > 0; st >>= 1) {
        if (tid < st) {
            float m1 = smx[tid], s1 = ssm[tid];
            float m2 = smx[tid + st], s2 = ssm[tid + st];
            if (m2 > m1) { smx[tid] = m2; ssm[tid] = s2 + s1 * expf(m1 - m2); }
            else         { ssm[tid] = s1 + s2 * expf(m2 - m1); }
        }
        __syncthreads();
    }
    const float mall = smx[0];
    const float sall = ssm[0];
    __syncthreads();

    // candidate threshold
    const float margin = ldexpf(sqrtf(hn2 * wmax2[0]), -8);
    const float thr = mall - margin;

    // exact rescue: recompute candidates in fp32
    float bv = -3.4e38f; int bi = 0x7fffffff;
    for (int j = tid; j < CV; j += 256) {
        if (row[j] >= thr) {
            const float* w = W + (size_t)j * CH;
            float dot = pb[j];
#pragma unroll 4
            for (int k = 0; k < CH; k++) dot = fmaf(sh[k], w[k], dot);
            if (dot > bv || (dot == bv && j < bi)) { bv = dot; bi = j; }
        }
    }
    smx[tid] = bv; sidx[tid] = bi;
    __syncthreads();
    for (int st = 128; st > 0; st >>= 1) {
        if (tid < st) {
            float v2 = smx[tid + st]; int i2 = sidx[tid + st];
            if (v2 > smx[tid] || (v2 == smx[tid] && i2 < sidx[tid])) { smx[tid] = v2; sidx[tid] = i2; }
        }
        __syncthreads();
    }
    if (tid == 0) {
        tok[b] = sidx[0];
        if (want_lp) lp[b] = smx[0] - (mall + logf(sall));
    }
}

// ---------------- hinge loss / accuracy reductions ----------------
__global__ void score_rows(const float* __restrict__ ts, const float* __restrict__ ds,
                           const float* __restrict__ lp,
                           float* __restrict__ rowloss, float* __restrict__ rowcorr)
{
    const int i = blockIdx.x;
    const float* trow = ts + (size_t)i * CB;
    const float* dr0 = ds + 0ULL * CB * CB + (size_t)i * CB;
    const float* dr1 = ds + 1ULL * CB * CB + (size_t)i * CB;
    const float* dr2 = ds + 2ULL * CB * CB + (size_t)i * CB;
    const float* dr3 = ds + 3ULL * CB * CB + (size_t)i * CB;

    float ls = 0.f, et = 0.f, e0 = 0.f, e1 = 0.f, e2 = 0.f, e3 = 0.f;
    for (int j = threadIdx.x; j < CB; j += 256) {
        const float t  = trow[j];
        const float a0 = dr0[j], a1 = dr1[j], a2 = dr2[j], a3 = dr3[j];
        float h = fmaxf(0.f, 1.f - t + a0) + fmaxf(0.f, 1.f - t + a1)
                + fmaxf(0.f, 1.f - t + a2) + fmaxf(0.f, 1.f - t + a3);
        ls += h * lp[j];
        et += expf(t); e0 += expf(a0); e1 += expf(a1); e2 += expf(a2); e3 += expf(a3);
    }
    __shared__ float red[6][256];
    red[0][threadIdx.x] = ls; red[1][threadIdx.x] = et;
    red[2][threadIdx.x] = e0; red[3][threadIdx.x] = e1;
    red[4][threadIdx.x] = e2; red[5][threadIdx.x] = e3;
    __syncthreads();
    for (int st = 128; st > 0; st >>= 1) {
        if (threadIdx.x < st)
#pragma unroll
            for (int q = 0; q < 6; q++) red[q][threadIdx.x] += red[q][threadIdx.x + st];
        __syncthreads();
    }
    if (threadIdx.x == 0) {
        rowloss[i] = red[0][0];
        const float tp = red[1][0] / (float)CB;
        const float mx = fmaxf(fmaxf(red[2][0], red[3][0]), fmaxf(red[4][0], red[5][0])) / (float)CB;
        rowcorr[i] = (tp >= mx) ? 1.f : 0.f;
    }
}

__global__ void final_reduce(const float* __restrict__ rowloss,
                             const float* __restrict__ rowcorr, float* __restrict__ out)
{
    __shared__ float s1[256], s2[256];
    float a = 0.f, b = 0.f;
    for (int i = threadIdx.x; i < CB; i += 256) { a += rowloss[i]; b += rowcorr[i]; }
    s1[threadIdx.x] = a; s2[threadIdx.x] = b;
    __syncthreads();
    for (int st = 128; st > 0; st >>= 1) {
        if (threadIdx.x < st) { s1[threadIdx.x] += s1[threadIdx.x + st]; s2[threadIdx.x] += s2[threadIdx.x + st]; }
        __syncthreads();
    }
    if (threadIdx.x == 0) {
        out[0] = -s1[0] / (float)((size_t)CB * CB);
        out[1] =  s2[0] / (float)CB;
    }
}

// ---------------------------------------------------------------------------
static inline void run_split(const float* src, float* hi, float* lo, size_t n)
{
    int n4 = (int)(n / 4);
    split_k<<<(n4 + 255) / 256, 256>>>((const float4*)src, (float4*)hi, (float4*)lo, n4);
}

extern "C" void kernel_launch(void* const* d_in, const int* in_sizes, int n_in,
                              void* d_out, int out_size)
{
    (void)in_sizes; (void)n_in; (void)out_size;
    const float* target   = (const float*)d_in[0];
    const float* distract = (const float*)d_in[1];
    const int*   sidx     = (const int*)d_in[2];
    const float* emb_s   = (const float*)d_in[4];
    const float* Wih_s   = (const float*)d_in[5];
    const float* Whh_s   = (const float*)d_in[6];
    const float* bih_s   = (const float*)d_in[7];
    const float* bhh_s   = (const float*)d_in[8];
    const float* aff_s_W = (const float*)d_in[9];
    const float* aff_s_b = (const float*)d_in[10];
    const float* probs_W = (const float*)d_in[11];
    const float* probs_b = (const float*)d_in[12];
    const float* emb_r   = (const float*)d_in[13];
    const float* Wih_r   = (const float*)d_in[14];
    const float* Whh_r   = (const float*)d_in[15];
    const float* bih_r   = (const float*)d_in[16];
    const float* bhh_r   = (const float*)d_in[17];
    const float* aff_r_W = (const float*)d_in[18];
    const float* aff_r_b = (const float*)d_in[19];
    float* out = (float*)d_out;

    cudaFuncSetAttribute(tmma_nt<3>, cudaFuncAttributeMaxDynamicSharedMemorySize, SMEM_BYTES);
    cudaFuncSetAttribute(tmma_nt<1>, cudaFuncAttributeMaxDynamicSharedMemorySize, SMEM_BYTES);

#define SYM(p, s) float* p; cudaGetSymbolAddress((void**)&p, s)
    SYM(pwh, g_pw_h); SYM(pwl, g_pw_l);
    SYM(wihsh, g_wihs_h); SYM(wihsl, g_wihs_l);
    SYM(whhsh, g_whhs_h); SYM(whhsl, g_whhs_l);
    SYM(wihrh, g_wihr_h); SYM(wihrl, g_wihr_l);
    SYM(whhrh, g_whhr_h); SYM(whhrl, g_whhr_l);
    SYM(affsh, g_affs_h); SYM(affsl, g_affs_l);
    SYM(affrh, g_affr_h); SYM(affrl, g_affr_l);
    SYM(tgth, g_tgt_h);   SYM(tgtl, g_tgt_l);
    SYM(dsth, g_dst_h);   SYM(dstl, g_dst_l);
    SYM(rh, g_r_h);       SYM(rl, g_r_l);
    SYM(hsh, g_hs_h);     SYM(hsl, g_hs_l);
    SYM(hrh, g_hr_h);     SYM(hrl, g_hr_l);
    SYM(xh, g_x_h);       SYM(xl, g_x_l);
    SYM(p_logits, g_logits); SYM(p_gates, g_gates);
    SYM(p_hs, g_hs); SYM(p_hr, g_hr); SYM(p_cs, g_cs); SYM(p_cr, g_cr);
    SYM(p_lp, g_lp); SYM(p_r, g_r); SYM(p_ts, g_ts); SYM(p_ds, g_ds);
    SYM(p_rowloss, g_rowloss); SYM(p_rowcorr, g_rowcorr);
    SYM(p_wmax2, g_wmax2);
#undef SYM
    int *p_msg, *p_tok0;
    cudaGetSymbolAddress((void**)&p_msg, g_msg);
    cudaGetSymbolAddress((void**)&p_tok0, g_tok0);

    // ---- prepass: split static operands into tf32 hi/lo planes ----
    run_split(probs_W,  pwh,   pwl,   (size_t)CV * CH);
    run_split(Wih_s,    wihsh, wihsl, (size_t)4 * CH * CE);
    run_split(Whh_s,    whhsh, whhsl, (size_t)4 * CH * CH);
    run_split(Wih_r,    wihrh, wihrl, (size_t)4 * CH * CE);
    run_split(Whh_r,    whhrh, whhrl, (size_t)4 * CH * CH);
    run_split(aff_s_W,  affsh, affsl, (size_t)CH * CF);
    run_split(aff_r_W,  affrh, affrl, (size_t)CF * CH);
    run_split(target,   tgth,  tgtl,  (size_t)CB * CF);
    run_split(distract, dsth,  dstl,  (size_t)CD * CB * CF);

    cudaMemsetAsync(p_cs, 0, (size_t)CB * CH * sizeof(float));
    cudaMemsetAsync(p_cr, 0, (size_t)CB * CH * sizeof(float));
    cudaMemsetAsync(hrh, 0, (size_t)CB * CH * sizeof(float));
    cudaMemsetAsync(hrl, 0, (size_t)CB * CH * sizeof(float));
    cudaMemsetAsync(p_wmax2, 0, sizeof(float));
    set_tok0<<<CB / 256, 256>>>(sidx, p_tok0);
    wnorms_max<<<(CV + 7) / 8, 256>>>(probs_W, p_wmax2);

    // h0 = target @ aff_s_W^T + aff_s_b  (full precision)
    tmma_nt<3><<<dim3(CH / BN, CB / BM), 256, SMEM_BYTES>>>(CB, CH,
        tgth, tgtl, CF, nullptr, nullptr, 0,
        affsh, affsl, nullptr, nullptr, aff_s_b, nullptr, p_hs);
    run_split(p_hs, hsh, hsl, (size_t)CB * CH);

    // ---- sender ----
    for (int t = 0; t < CL; t++) {
        const int* tokidx = (t == 0) ? p_tok0 : (p_msg + (t - 1) * CB);
        gather_split_k<<<(CB * CE / 4 + 255) / 256, 256>>>(tokidx, emb_s, xh, xl);
        tmma_nt<3><<<dim3(4 * CH / BN, CB / BM), 256, SMEM_BYTES>>>(CB, 4 * CH,
            xh, xl, CE, hsh, hsl, CH,
            wihsh, wihsl, whhsh, whhsl, bih_s, bhh_s, p_gates);
        lstm_cell_split<<<(CB * CH) / 256, 256>>>(p_gates, p_cs, p_hs, hsh, hsl);
        // phase-1 logits: single tf32
        tmma_nt<1><<<dim3((CV + BN - 1) / BN, CB / BM), 256, SMEM_BYTES>>>(CB, CV,
            hsh, nullptr, CH, nullptr, nullptr, 0,
            pwh, nullptr, nullptr, nullptr, probs_b, nullptr, p_logits);
        // argmax with exact fp32 rescue
        logits_argmax<<<CB, 256>>>(p_logits, p_hs, probs_W, probs_b, p_wmax2,
                                   p_msg + t * CB, p_lp, (t == CL - 1) ? 1 : 0);
    }

    // ---- receiver ----
    for (int t = 0; t < CL; t++) {
        gather_split_k<<<(CB * CE / 4 + 255) / 256, 256>>>(p_msg + t * CB, emb_r, xh, xl);
        tmma_nt<3><<<dim3(4 * CH / BN, CB / BM), 256, SMEM_BYTES>>>(CB, 4 * CH,
            xh, xl, CE, hrh, hrl, CH,
            wihrh, wihrl, whhrh, whhrl, bih_r, bhh_r, p_gates);
        lstm_cell_split<<<(CB * CH) / 256, 256>>>(p_gates, p_cr, p_hr, hrh, hrl);
    }

    // r = hr @ aff_r_W^T + aff_r_b
    tmma_nt<3><<<dim3(CF / BN, CB / BM), 256, SMEM_BYTES>>>(CB, CF,
        hrh, hrl, CH, nullptr, nullptr, 0,
        affrh, affrl, nullptr, nullptr, aff_r_b, nullptr, p_r);
    run_split(p_r, rh, rl, (size_t)CB * CF);

    // ts = target @ r^T ; ds = distractors @ r^T
    tmma_nt<3><<<dim3(CB / BN, CB / BM), 256, SMEM_BYTES>>>(CB, CB,
        tgth, tgtl, CF, nullptr, nullptr, 0,
        rh, rl, nullptr, nullptr, nullptr, nullptr, p_ts);
    tmma_nt<3><<<dim3(CB / BN, (CD * CB) / BM), 256, SMEM_BYTES>>>(CD * CB, CB,
        dsth, dstl, CF, nullptr, nullptr, 0,
        rh, rl, nullptr, nullptr, nullptr, nullptr, p_ds);

    score_rows<<<CB, 256>>>(p_ts, p_ds, p_lp, p_rowloss, p_rowcorr);
    final_reduce<<<1, 256>>>(p_rowloss, p_rowcorr, out);
}

// round 6
// speedup vs baseline: 1.7736x; 1.1115x over previous
#include <cuda_runtime.h>
#include <cstdint>

typedef unsigned long long u64;
typedef uint32_t u32;

constexpr int CB = 1024;   // batch
constexpr int CF = 4096;   // feature
constexpr int CV = 20000;  // vocab
constexpr int CE = 512;    // embed dim
constexpr int CH = 1024;   // hidden
constexpr int CL = 20;     // sentence length
constexpr int CD = 4;      // distractors

// ---------------- GEMM tiling ----------------
constexpr int BM = 128, BN = 128, BK = 16;
constexpr int APAD = 24;                 // row stride (floats): conflict-free LDS.64 frags
constexpr int TFL = BM * APAD;           // 3072 floats per plane tile
constexpr int SMEM3 = 2 * 4 * TFL * 4;   // 98304 B (stages x [Ah,Al,Bh,Bl])
constexpr int SMEM1 = 2 * 2 * TFL * 4;   // 49152 B (stages x [Ah,Bh])

// ---------------- scratch (static device globals; no allocation) ----------------
#define DG __device__ __align__(256)
// tf32 hi/lo planes
DG float g_pw_h[(size_t)CV * CH];    DG float g_pw_l[(size_t)CV * CH];
DG float g_wihs_h[4 * CH * CE];      DG float g_wihs_l[4 * CH * CE];
DG float g_whhs_h[4 * CH * CH];      DG float g_whhs_l[4 * CH * CH];
DG float g_wihr_h[4 * CH * CE];      DG float g_wihr_l[4 * CH * CE];
DG float g_whhr_h[4 * CH * CH];      DG float g_whhr_l[4 * CH * CH];
DG float g_affs_h[CH * CF];          DG float g_affs_l[CH * CF];
DG float g_affr_h[CF * CH];          DG float g_affr_l[CF * CH];
DG float g_tgt_h[(size_t)CB * CF];   DG float g_tgt_l[(size_t)CB * CF];
DG float g_dst_h[(size_t)CD * CB * CF]; DG float g_dst_l[(size_t)CD * CB * CF];
DG float g_r_h[(size_t)CB * CF];     DG float g_r_l[(size_t)CB * CF];
DG float g_hs_h[CB * CH];            DG float g_hs_l[CB * CH];
DG float g_hr_h[CB * CH];            DG float g_hr_l[CB * CH];
DG float g_x_h[CB * CE];             DG float g_x_l[CB * CE];
DG float g_xr_h[CB * CE];            DG float g_xr_l[CB * CE];   // receiver-stream gather
// raw buffers
DG float g_logits[(size_t)CB * CV];
DG float g_gates[(size_t)CB * 4 * CH];
DG float g_gates_r[(size_t)CB * 4 * CH];                          // receiver-stream gates
DG float g_hs[CB * CH];
DG float g_hr[CB * CH];
DG float g_cs[CB * CH];
DG float g_cr[CB * CH];
DG float g_lp[CB];
DG float g_r[(size_t)CB * CF];
DG float g_ts[(size_t)CB * CB];
DG float g_ds[(size_t)CD * CB * CB];
DG float g_rowloss[CB];
DG float g_rowcorr[CB];
DG float g_wmax2[1];
DG int   g_msg[CL * CB];
DG int   g_tok0[CB];

// ---------------- low-level helpers ----------------
__device__ __forceinline__ u32 s2u(const void* p) {
    u32 a; asm("{ .reg .u64 t; cvta.to.shared.u64 t, %1; cvt.u32.u64 %0, t; }" : "=r"(a) : "l"(p));
    return a;
}
__device__ __forceinline__ float tf32r(float x) {
    float r; asm("cvt.rna.tf32.f32 %0, %1;" : "=f"(r) : "f"(x)); return r;
}
__device__ __forceinline__ void cp16(u32 dst, const void* src, bool v) {
    int sz = v ? 16 : 0;
    asm volatile("cp.async.cg.shared.global [%0], [%1], 16, %2;" :: "r"(dst), "l"(src), "r"(sz) : "memory");
}
#define CP_COMMIT() asm volatile("cp.async.commit_group;" ::: "memory")

__device__ __forceinline__ void mma8(float* d, const u32* a, const u32* b) {
    asm volatile(
        "mma.sync.aligned.m16n8k8.row.col.f32.tf32.tf32.f32 "
        "{%0,%1,%2,%3}, {%4,%5,%6,%7}, {%8,%9}, {%0,%1,%2,%3};"
        : "+f"(d[0]), "+f"(d[1]), "+f"(d[2]), "+f"(d[3])
        : "r"(a[0]), "r"(a[1]), "r"(a[2]), "r"(a[3]), "r"(b[0]), "r"(b[1]));
}

// ---------------------------------------------------------------------------
// NT GEMM on pre-split tf32 planes, K-permuted LDS.64 fragment loads.
// K-slot permutation: slot t <- k=2t, slot t+4 <- k=2t+1 (applied to BOTH
// A and B fragments -> contraction unchanged).
// NPASS=3: C = Ah*Bh + Ah*Bl + Al*Bh ; NPASS=1: C = Ah*Bh.
// ---------------------------------------------------------------------------
template<int NPASS>
__global__ __launch_bounds__(256, 2)
void tmma_nt(int M, int N,
             const float* __restrict__ A1h, const float* __restrict__ A1l, int K1,
             const float* __restrict__ A2h, const float* __restrict__ A2l, int K2,
             const float* __restrict__ B1h, const float* __restrict__ B1l,
             const float* __restrict__ B2h, const float* __restrict__ B2l,
             const float* __restrict__ bias1, const float* __restrict__ bias2,
             float* __restrict__ C)
{
    extern __shared__ float sm[];
    constexpr int PL = (NPASS == 3) ? 4 : 2;
    constexpr int OAH = 0, OAL = TFL, OBH = (NPASS == 3 ? 2 : 1) * TFL, OBL = 3 * TFL;

    const int tid  = threadIdx.x;
    const int wid  = tid >> 5;
    const int lane = tid & 31;
    const int g    = lane >> 2;
    const int t    = lane & 3;
    const int wm   = (wid & 3) * 32;    // 4 M-warps
    const int wn   = (wid >> 2) * 64;   // 2 N-warps
    const int bn0  = blockIdx.x * BN;
    const int bm0  = blockIdx.y * BM;

    const int nk1 = K1 / BK;
    const int nk2 = A2h ? (K2 / BK) : 0;
    const int nkt = nk1 + nk2;

    auto load_stage = [&](int gkt, int stage) {
        const float *Ah, *Al, *Bh, *Bl; int K, kt;
        if (gkt < nk1) { Ah = A1h; Al = A1l; Bh = B1h; Bl = B1l; K = K1; kt = gkt; }
        else           { Ah = A2h; Al = A2l; Bh = B2h; Bl = B2l; K = K2; kt = gkt - nk1; }
        const int koff = kt * BK;
        float* st = sm + stage * PL * TFL;
        u32 uah = s2u(st + OAH), ubh = s2u(st + OBH);
        u32 ual = s2u(st + OAL), ubl = s2u(st + OBL);
#pragma unroll
        for (int it = 0; it < 2; it++) {
            int c = tid + it * 256;          // 0..511 (128 rows x 4 16B-chunks)
            int row = c >> 2, ch = c & 3;
            u32 off = (u32)(row * APAD + ch * 4) * 4;
            const size_t ga = (size_t)(bm0 + row) * K + koff + ch * 4;
            cp16(uah + off, Ah + ga, true);
            if (NPASS == 3) cp16(ual + off, Al + ga, true);
            bool v = (bn0 + row) < N;
            const size_t gb = (size_t)(v ? (bn0 + row) : 0) * K + koff + ch * 4;
            cp16(ubh + off, Bh + gb, v);
            if (NPASS == 3) cp16(ubl + off, Bl + gb, v);
        }
        CP_COMMIT();
    };

    float d[2][8][4];
#pragma unroll
    for (int i = 0; i < 2; i++)
#pragma unroll
        for (int j = 0; j < 8; j++)
#pragma unroll
            for (int q = 0; q < 4; q++) d[i][j][q] = 0.f;

    load_stage(0, 0);

    for (int s = 0; s < nkt; s++) {
        if (s + 1 < nkt) {
            load_stage(s + 1, (s + 1) & 1);
            asm volatile("cp.async.wait_group 1;" ::: "memory");
        } else {
            asm volatile("cp.async.wait_group 0;" ::: "memory");
        }
        __syncthreads();

        const float* st  = sm + (s & 1) * PL * TFL;
        const float* pAh = st + OAH;
        const float* pAl = st + OAL;
        const float* pBh = st + OBH;
        const float* pBl = st + OBL;

#pragma unroll
        for (int kk = 0; kk < BK; kk += 8) {
            // A fragments: row g and g+8, adjacent k-pair (2t, 2t+1)
            float2 aH[2][2], aL[2][2];
#pragma unroll
            for (int mt = 0; mt < 2; mt++) {
                const int base = (wm + mt * 16 + g) * APAD + kk + 2 * t;
                aH[mt][0] = *(const float2*)(pAh + base);
                aH[mt][1] = *(const float2*)(pAh + base + 8 * APAD);
                if (NPASS == 3) {
                    aL[mt][0] = *(const float2*)(pAl + base);
                    aL[mt][1] = *(const float2*)(pAl + base + 8 * APAD);
                }
            }
#pragma unroll
            for (int nt = 0; nt < 8; nt++) {
                const int bidx = (wn + nt * 8 + g) * APAD + kk + 2 * t;
                float2 bHf = *(const float2*)(pBh + bidx);
                u32 bH[2] = {__float_as_uint(bHf.x), __float_as_uint(bHf.y)};
                u32 bL[2];
                if (NPASS == 3) {
                    float2 bLf = *(const float2*)(pBl + bidx);
                    bL[0] = __float_as_uint(bLf.x); bL[1] = __float_as_uint(bLf.y);
                }
#pragma unroll
                for (int mt = 0; mt < 2; mt++) {
                    u32 aH4[4] = {__float_as_uint(aH[mt][0].x), __float_as_uint(aH[mt][1].x),
                                  __float_as_uint(aH[mt][0].y), __float_as_uint(aH[mt][1].y)};
                    mma8(d[mt][nt], aH4, bH);
                    if (NPASS == 3) {
                        mma8(d[mt][nt], aH4, bL);
                        u32 aL4[4] = {__float_as_uint(aL[mt][0].x), __float_as_uint(aL[mt][1].x),
                                      __float_as_uint(aL[mt][0].y), __float_as_uint(aL[mt][1].y)};
                        mma8(d[mt][nt], aL4, bH);
                    }
                }
            }
        }
        __syncthreads();
    }

    // epilogue
#pragma unroll
    for (int nt = 0; nt < 8; nt++) {
        const int cb = bn0 + wn + nt * 8;
        if (cb >= N) continue;
        const int col = cb + 2 * t;
        float b0 = 0.f, b1 = 0.f;
        if (bias1) { b0 += bias1[col]; b1 += bias1[col + 1]; }
        if (bias2) { b0 += bias2[col]; b1 += bias2[col + 1]; }
#pragma unroll
        for (int mt = 0; mt < 2; mt++) {
            const int row = bm0 + wm + mt * 16 + g;
            float2 v0 = make_float2(d[mt][nt][0] + b0, d[mt][nt][1] + b1);
            float2 v1 = make_float2(d[mt][nt][2] + b0, d[mt][nt][3] + b1);
            *(float2*)(C + (size_t)row * N + col) = v0;
            *(float2*)(C + (size_t)(row + 8) * N + col) = v1;
        }
    }
}

// ---------------- split / gather / lstm elementwise ----------------
__global__ void split_k(const float4* __restrict__ src, float4* __restrict__ hi,
                        float4* __restrict__ lo, int n4)
{
    int i = blockIdx.x * blockDim.x + threadIdx.x;
    if (i >= n4) return;
    float4 s = src[i];
    float4 h, l;
    h.x = tf32r(s.x); l.x = tf32r(s.x - h.x);
    h.y = tf32r(s.y); l.y = tf32r(s.y - h.y);
    h.z = tf32r(s.z); l.z = tf32r(s.z - h.z);
    h.w = tf32r(s.w); l.w = tf32r(s.w - h.w);
    hi[i] = h; lo[i] = l;
}

__global__ void gather_split_k(const int* __restrict__ tok, const float* __restrict__ emb,
                               float* __restrict__ xh, float* __restrict__ xl)
{
    int i = blockIdx.x * blockDim.x + threadIdx.x;
    if (i >= CB * (CE / 4)) return;
    int b = i / (CE / 4), j = (i % (CE / 4)) * 4;
    float4 e = *(const float4*)(emb + (size_t)tok[b] * CE + j);
    float4 h, l;
    h.x = tf32r(e.x); l.x = tf32r(e.x - h.x);
    h.y = tf32r(e.y); l.y = tf32r(e.y - h.y);
    h.z = tf32r(e.z); l.z = tf32r(e.z - h.z);
    h.w = tf32r(e.w); l.w = tf32r(e.w - h.w);
    *(float4*)(xh + (size_t)b * CE + j) = h;
    *(float4*)(xl + (size_t)b * CE + j) = l;
}

__global__ void lstm_cell_split(const float* __restrict__ gates, float* __restrict__ c,
                                float* __restrict__ hraw,
                                float* __restrict__ hhi, float* __restrict__ hlo)
{
    const int t = blockIdx.x * blockDim.x + threadIdx.x;
    if (t >= CB * CH) return;
    const int b = t >> 10, j = t & 1023;
    const float* g = gates + (size_t)b * (4 * CH);
    const float gi = g[j], gf = g[CH + j], gg = g[2 * CH + j], go = g[3 * CH + j];
    const float ig = 1.f / (1.f + __expf(-gi));
    const float fg = 1.f / (1.f + __expf(-gf));
    const float og = 1.f / (1.f + __expf(-go));
    const float cn = fg * c[t] + ig * tanhf(gg);
    c[t] = cn;
    const float h = og * tanhf(cn);
    hraw[t] = h;
    const float hh = tf32r(h);
    hhi[t] = hh;
    hlo[t] = tf32r(h - hh);
}

__global__ void set_tok0(const int* __restrict__ sidx, int* __restrict__ tok)
{
    const int i = blockIdx.x * blockDim.x + threadIdx.x;
    if (i < CB) tok[i] = sidx[0];
}

// max squared row-norm of probs_W
__global__ void wnorms_max(const float* __restrict__ W, float* __restrict__ wmax2)
{
    const int row = blockIdx.x * 8 + (threadIdx.x >> 5);
    const int lane = threadIdx.x & 31;
    if (row >= CV) return;
    const float* w = W + (size_t)row * CH;
    float s = 0.f;
    for (int k = lane; k < CH; k += 32) { float v = w[k]; s += v * v; }
#pragma unroll
    for (int st = 16; st > 0; st >>= 1) s += __shfl_xor_sync(0xffffffff, s, st);
    if (lane == 0) atomicMax((int*)wmax2, __float_as_int(s));
}

// argmax over tf32 logits + exact fp32 rescue of near-max candidates
__global__ void logits_argmax(const float* __restrict__ logits,
                              const float* __restrict__ h,
                              const float* __restrict__ W,
                              const float* __restrict__ pb,
                              const float* __restrict__ wmax2,
                              int* __restrict__ tok, float* __restrict__ lp, int want_lp)
{
    const int b = blockIdx.x;
    const int tid = threadIdx.x;
    __shared__ float sh[CH];
    __shared__ float smx[256], ssm[256];
    __shared__ int   sidx[256];

    float nrm = 0.f;
    for (int i = tid; i < CH; i += 256) { float v = h[(size_t)b * CH + i]; sh[i] = v; nrm += v * v; }
    smx[tid] = nrm;
    __syncthreads();
    for (int st = 128; st > 0; st >>= 1) {
        if (tid < st) smx[tid] += smx[tid + st];
        __syncthreads();
    }
    const float hn2 = smx[0];
    __syncthreads();

    const float* row = logits + (size_t)b * CV;
    float m = -3.4e38f, s = 0.f;
    for (int j = tid; j < CV; j += 256) {
        float x = row[j];
        if (x > m) {
            if (want_lp) s = s * expf(m - x) + 1.f;
            m = x;
        } else if (want_lp) {
            s += expf(x - m);
        }
    }
    smx[tid] = m; ssm[tid] = s;
    __syncthreads();
    for (int st = 128; st > 0; st >>= 1) {
        if (tid < st) {
            float m1 = smx[tid], s1 = ssm[tid];
            float m2 = smx[tid + st], s2 = ssm[tid + st];
            if (m2 > m1) { smx[tid] = m2; ssm[tid] = s2 + s1 * expf(m1 - m2); }
            else         { ssm[tid] = s1 + s2 * expf(m2 - m1); }
        }
        __syncthreads();
    }
    const float mall = smx[0];
    const float sall = ssm[0];
    __syncthreads();

    const float margin = ldexpf(sqrtf(hn2 * wmax2[0]), -8);
    const float thr = mall - margin;

    float bv = -3.4e38f; int bi = 0x7fffffff;
    for (int j = tid; j < CV; j += 256) {
        if (row[j] >= thr) {
            const float* w = W + (size_t)j * CH;
            float dot = pb[j];
#pragma unroll 4
            for (int k = 0; k < CH; k++) dot = fmaf(sh[k], w[k], dot);
            if (dot > bv || (dot == bv && j < bi)) { bv = dot; bi = j; }
        }
    }
    smx[tid] = bv; sidx[tid] = bi;
    __syncthreads();
    for (int st = 128; st > 0; st >>= 1) {
        if (tid < st) {
            float v2 = smx[tid + st]; int i2 = sidx[tid + st];
            if (v2 > smx[tid] || (v2 == smx[tid] && i2 < sidx[tid])) { smx[tid] = v2; sidx[tid] = i2; }
        }
        __syncthreads();
    }
    if (tid == 0) {
        tok[b] = sidx[0];
        if (want_lp) lp[b] = smx[0] - (mall + logf(sall));
    }
}

// ---------------- hinge loss / accuracy reductions ----------------
__global__ void score_rows(const float* __restrict__ ts, const float* __restrict__ ds,
                           const float* __restrict__ lp,
                           float* __restrict__ rowloss, float* __restrict__ rowcorr)
{
    const int i = blockIdx.x;
    const float* trow = ts + (size_t)i * CB;
    const float* dr0 = ds + 0ULL * CB * CB + (size_t)i * CB;
    const float* dr1 = ds + 1ULL * CB * CB + (size_t)i * CB;
    const float* dr2 = ds + 2ULL * CB * CB + (size_t)i * CB;
    const float* dr3 = ds + 3ULL * CB * CB + (size_t)i * CB;

    float ls = 0.f, et = 0.f, e0 = 0.f, e1 = 0.f, e2 = 0.f, e3 = 0.f;
    for (int j = threadIdx.x; j < CB; j += 256) {
        const float t  = trow[j];
        const float a0 = dr0[j], a1 = dr1[j], a2 = dr2[j], a3 = dr3[j];
        float h = fmaxf(0.f, 1.f - t + a0) + fmaxf(0.f, 1.f - t + a1)
                + fmaxf(0.f, 1.f - t + a2) + fmaxf(0.f, 1.f - t + a3);
        ls += h * lp[j];
        et += expf(t); e0 += expf(a0); e1 += expf(a1); e2 += expf(a2); e3 += expf(a3);
    }
    __shared__ float red[6][256];
    red[0][threadIdx.x] = ls; red[1][threadIdx.x] = et;
    red[2][threadIdx.x] = e0; red[3][threadIdx.x] = e1;
    red[4][threadIdx.x] = e2; red[5][threadIdx.x] = e3;
    __syncthreads();
    for (int st = 128; st > 0; st >>= 1) {
        if (threadIdx.x < st)
#pragma unroll
            for (int q = 0; q < 6; q++) red[q][threadIdx.x] += red[q][threadIdx.x + st];
        __syncthreads();
    }
    if (threadIdx.x == 0) {
        rowloss[i] = red[0][0];
        const float tp = red[1][0] / (float)CB;
        const float mx = fmaxf(fmaxf(red[2][0], red[3][0]), fmaxf(red[4][0], red[5][0])) / (float)CB;
        rowcorr[i] = (tp >= mx) ? 1.f : 0.f;
    }
}

__global__ void final_reduce(const float* __restrict__ rowloss,
                             const float* __restrict__ rowcorr, float* __restrict__ out)
{
    __shared__ float s1[256], s2[256];
    float a = 0.f, b = 0.f;
    for (int i = threadIdx.x; i < CB; i += 256) { a += rowloss[i]; b += rowcorr[i]; }
    s1[threadIdx.x] = a; s2[threadIdx.x] = b;
    __syncthreads();
    for (int st = 128; st > 0; st >>= 1) {
        if (threadIdx.x < st) { s1[threadIdx.x] += s1[threadIdx.x + st]; s2[threadIdx.x] += s2[threadIdx.x + st]; }
        __syncthreads();
    }
    if (threadIdx.x == 0) {
        out[0] = -s1[0] / (float)((size_t)CB * CB);
        out[1] =  s2[0] / (float)CB;
    }
}

// ---------------------------------------------------------------------------
static inline void run_split(const float* src, float* hi, float* lo, size_t n)
{
    int n4 = (int)(n / 4);
    split_k<<<(n4 + 255) / 256, 256>>>((const float4*)src, (float4*)hi, (float4*)lo, n4);
}

extern "C" void kernel_launch(void* const* d_in, const int* in_sizes, int n_in,
                              void* d_out, int out_size)
{
    (void)in_sizes; (void)n_in; (void)out_size;
    const float* target   = (const float*)d_in[0];
    const float* distract = (const float*)d_in[1];
    const int*   sidx     = (const int*)d_in[2];
    const float* emb_s   = (const float*)d_in[4];
    const float* Wih_s   = (const float*)d_in[5];
    const float* Whh_s   = (const float*)d_in[6];
    const float* bih_s   = (const float*)d_in[7];
    const float* bhh_s   = (const float*)d_in[8];
    const float* aff_s_W = (const float*)d_in[9];
    const float* aff_s_b = (const float*)d_in[10];
    const float* probs_W = (const float*)d_in[11];
    const float* probs_b = (const float*)d_in[12];
    const float* emb_r   = (const float*)d_in[13];
    const float* Wih_r   = (const float*)d_in[14];
    const float* Whh_r   = (const float*)d_in[15];
    const float* bih_r   = (const float*)d_in[16];
    const float* bhh_r   = (const float*)d_in[17];
    const float* aff_r_W = (const float*)d_in[18];
    const float* aff_r_b = (const float*)d_in[19];
    float* out = (float*)d_out;

    // one-time host resources (no device memory)
    static cudaStream_t s2 = nullptr;
    static cudaEvent_t evFork = nullptr, evJoin = nullptr, evTok[CL];
    if (!s2) {
        cudaStreamCreateWithFlags(&s2, cudaStreamNonBlocking);
        cudaEventCreateWithFlags(&evFork, cudaEventDisableTiming);
        cudaEventCreateWithFlags(&evJoin, cudaEventDisableTiming);
        for (int t = 0; t < CL; t++) cudaEventCreateWithFlags(&evTok[t], cudaEventDisableTiming);
    }

    cudaFuncSetAttribute(tmma_nt<3>, cudaFuncAttributeMaxDynamicSharedMemorySize, SMEM3);
    cudaFuncSetAttribute(tmma_nt<1>, cudaFuncAttributeMaxDynamicSharedMemorySize, SMEM1);

#define SYM(p, s) float* p; cudaGetSymbolAddress((void**)&p, s)
    SYM(pwh, g_pw_h); SYM(pwl, g_pw_l);
    SYM(wihsh, g_wihs_h); SYM(wihsl, g_wihs_l);
    SYM(whhsh, g_whhs_h); SYM(whhsl, g_whhs_l);
    SYM(wihrh, g_wihr_h); SYM(wihrl, g_wihr_l);
    SYM(whhrh, g_whhr_h); SYM(whhrl, g_whhr_l);
    SYM(affsh, g_affs_h); SYM(affsl, g_affs_l);
    SYM(affrh, g_affr_h); SYM(affrl, g_affr_l);
    SYM(tgth, g_tgt_h);   SYM(tgtl, g_tgt_l);
    SYM(dsth, g_dst_h);   SYM(dstl, g_dst_l);
    SYM(rh, g_r_h);       SYM(rl, g_r_l);
    SYM(hsh, g_hs_h);     SYM(hsl, g_hs_l);
    SYM(hrh, g_hr_h);     SYM(hrl, g_hr_l);
    SYM(xh, g_x_h);       SYM(xl, g_x_l);
    SYM(xrh, g_xr_h);     SYM(xrl, g_xr_l);
    SYM(p_logits, g_logits); SYM(p_gates, g_gates); SYM(p_gates_r, g_gates_r);
    SYM(p_hs, g_hs); SYM(p_hr, g_hr); SYM(p_cs, g_cs); SYM(p_cr, g_cr);
    SYM(p_lp, g_lp); SYM(p_r, g_r); SYM(p_ts, g_ts); SYM(p_ds, g_ds);
    SYM(p_rowloss, g_rowloss); SYM(p_rowcorr, g_rowcorr);
    SYM(p_wmax2, g_wmax2);
#undef SYM
    int *p_msg, *p_tok0;
    cudaGetSymbolAddress((void**)&p_msg, g_msg);
    cudaGetSymbolAddress((void**)&p_tok0, g_tok0);

    // ---- prepass: split static operands into tf32 hi/lo planes ----
    run_split(probs_W,  pwh,   pwl,   (size_t)CV * CH);
    run_split(Wih_s,    wihsh, wihsl, (size_t)4 * CH * CE);
    run_split(Whh_s,    whhsh, whhsl, (size_t)4 * CH * CH);
    run_split(Wih_r,    wihrh, wihrl, (size_t)4 * CH * CE);
    run_split(Whh_r,    whhrh, whhrl, (size_t)4 * CH * CH);
    run_split(aff_s_W,  affsh, affsl, (size_t)CH * CF);
    run_split(aff_r_W,  affrh, affrl, (size_t)CF * CH);
    run_split(target,   tgth,  tgtl,  (size_t)CB * CF);
    run_split(distract, dsth,  dstl,  (size_t)CD * CB * CF);

    cudaMemsetAsync(p_cs, 0, (size_t)CB * CH * sizeof(float));
    cudaMemsetAsync(p_cr, 0, (size_t)CB * CH * sizeof(float));
    cudaMemsetAsync(hrh, 0, (size_t)CB * CH * sizeof(float));
    cudaMemsetAsync(hrl, 0, (size_t)CB * CH * sizeof(float));
    cudaMemsetAsync(p_wmax2, 0, sizeof(float));
    set_tok0<<<CB / 256, 256>>>(sidx, p_tok0);
    wnorms_max<<<(CV + 7) / 8, 256>>>(probs_W, p_wmax2);

    // fork receiver stream (after receiver-state memsets are queued)
    cudaEventRecord(evFork, 0);
    cudaStreamWaitEvent(s2, evFork, 0);

    // h0 = target @ aff_s_W^T + aff_s_b
    tmma_nt<3><<<dim3(CH / BN, CB / BM), 256, SMEM3>>>(CB, CH,
        tgth, tgtl, CF, nullptr, nullptr, 0,
        affsh, affsl, nullptr, nullptr, aff_s_b, nullptr, p_hs);
    run_split(p_hs, hsh, hsl, (size_t)CB * CH);

    // ---- sender (stream 0) ----
    for (int t = 0; t < CL; t++) {
        const int* tokidx = (t == 0) ? p_tok0 : (p_msg + (t - 1) * CB);
        gather_split_k<<<(CB * CE / 4 + 255) / 256, 256>>>(tokidx, emb_s, xh, xl);
        tmma_nt<3><<<dim3(4 * CH / BN, CB / BM), 256, SMEM3>>>(CB, 4 * CH,
            xh, xl, CE, hsh, hsl, CH,
            wihsh, wihsl, whhsh, whhsl, bih_s, bhh_s, p_gates);
        lstm_cell_split<<<(CB * CH) / 256, 256>>>(p_gates, p_cs, p_hs, hsh, hsl);
        tmma_nt<1><<<dim3((CV + BN - 1) / BN, CB / BM), 256, SMEM1>>>(CB, CV,
            hsh, nullptr, CH, nullptr, nullptr, 0,
            pwh, nullptr, nullptr, nullptr, probs_b, nullptr, p_logits);
        logits_argmax<<<CB, 256>>>(p_logits, p_hs, probs_W, probs_b, p_wmax2,
                                   p_msg + t * CB, p_lp, (t == CL - 1) ? 1 : 0);
        cudaEventRecord(evTok[t], 0);
    }

    // ---- receiver (stream s2, overlapped with sender) ----
    for (int t = 0; t < CL; t++) {
        cudaStreamWaitEvent(s2, evTok[t], 0);
        gather_split_k<<<(CB * CE / 4 + 255) / 256, 256, 0, s2>>>(p_msg + t * CB, emb_r, xrh, xrl);
        tmma_nt<3><<<dim3(4 * CH / BN, CB / BM), 256, SMEM3, s2>>>(CB, 4 * CH,
            xrh, xrl, CE, hrh, hrl, CH,
            wihrh, wihrl, whhrh, whhrl, bih_r, bhh_r, p_gates_r);
        lstm_cell_split<<<(CB * CH) / 256, 256, 0, s2>>>(p_gates_r, p_cr, p_hr, hrh, hrl);
    }
    cudaEventRecord(evJoin, s2);
    cudaStreamWaitEvent(0, evJoin, 0);

    // r = hr @ aff_r_W^T + aff_r_b
    tmma_nt<3><<<dim3(CF / BN, CB / BM), 256, SMEM3>>>(CB, CF,
        hrh, hrl, CH, nullptr, nullptr, 0,
        affrh, affrl, nullptr, nullptr, aff_r_b, nullptr, p_r);
    run_split(p_r, rh, rl, (size_t)CB * CF);

    // ts = target @ r^T ; ds = distractors @ r^T
    tmma_nt<3><<<dim3(CB / BN, CB / BM), 256, SMEM3>>>(CB, CB,
        tgth, tgtl, CF, nullptr, nullptr, 0,
        rh, rl, nullptr, nullptr, nullptr, nullptr, p_ts);
    tmma_nt<3><<<dim3(CB / BN, (CD * CB) / BM), 256, SMEM3>>>(CD * CB, CB,
        dsth, dstl, CF, nullptr, nullptr, 0,
        rh, rl, nullptr, nullptr, nullptr, nullptr, p_ds);

    score_rows<<<CB, 256>>>(p_ts, p_ds, p_lp, p_rowloss, p_rowcorr);
    final_reduce<<<1, 256>>>(p_rowloss, p_rowcorr, out);
}